// round 9
// baseline (speedup 1.0000x reference)
#include <cuda_runtime.h>

#define NNODE 50000
#define NEDGE 800000
#define ETOT  (NNODE + NEDGE)   // edges + self loops
#define FEAT  128               // H*C
#define HH    4
#define NEG_SLOPE 0.2f

// ---- scratch (static device globals; no allocation allowed) ----
__device__ float g_xl[NNODE * FEAT];   // 25.6 MB
__device__ float g_xr[NNODE * FEAT];   // 25.6 MB
__device__ float g_ex[ETOT * HH];      // 13.6 MB  exp(logit) per edge/head
__device__ float g_den[NNODE * HH];    // softmax denominators
__device__ float g_alpha_sink[ETOT * HH];  // fallback alpha target
__device__ int   g_ei32[2 * NEDGE];    // normalized int32 edge index
__device__ int   g_is64;               // detected dtype flag

// ---------------------------------------------------------------
// K-1a: detect edge_index dtype. Interpreting int32 data as int64
// fuses index pairs -> huge values; int64 data stays in [0, N).
// ---------------------------------------------------------------
__global__ void k_detect(const void* __restrict__ ei) {
    if (threadIdx.x == 0 && blockIdx.x == 0) {
        const long long* p64 = (const long long*)ei;
        int is64 = 1;
        #pragma unroll
        for (int i = 0; i < 32; i++) {
            long long v = p64[i];
            if (v < 0 || v >= NNODE) { is64 = 0; break; }
        }
        g_is64 = is64;
    }
}

// ---------------------------------------------------------------
// K-1b: normalize edge index to int32 (handles both dtypes)
// ---------------------------------------------------------------
__global__ void k_convert(const void* __restrict__ ei) {
    int i = blockIdx.x * blockDim.x + threadIdx.x;
    if (i < 2 * NEDGE) {
        int v = g_is64 ? (int)((const long long*)ei)[i]
                       : ((const int*)ei)[i];
        g_ei32[i] = v;
    }
}

// ---------------------------------------------------------------
// K0: zero the output accumulator region and the denominators
// ---------------------------------------------------------------
__global__ void k_zero(float* __restrict__ out_acc) {
    int i = blockIdx.x * blockDim.x + threadIdx.x;
    if (i < NNODE * FEAT) out_acc[i] = 0.0f;
    if (i < NNODE * HH)   g_den[i]   = 0.0f;
}

// ---------------------------------------------------------------
// K1: FUSED dual projection GEMM: one block computes the 64x128
// output tile of BOTH xl (x@Wl) and xr (x@Wr), staging the x tile
// once. 256 threads as 16x16; each thread: two 4x8 micro-tiles.
// ---------------------------------------------------------------
__global__ void k_gemm(const float* __restrict__ x,
                       const float* __restrict__ Wl,
                       const float* __restrict__ Wr) {
    __shared__ float xs[64][17];     // +1 pad
    __shared__ float wsl[16][128];
    __shared__ float wsr[16][128];

    const int tid = threadIdx.x;
    const int tx  = tid & 15;        // output col group (8 cols)
    const int ty  = tid >> 4;        // output row group (4 rows)
    const int row0 = blockIdx.x * 64;

    float accl[4][8] = {};
    float accr[4][8] = {};

    for (int k0 = 0; k0 < 128; k0 += 16) {
        {
            int r = tid >> 2;
            int c = (tid & 3) * 4;
            float4 v = make_float4(0.f, 0.f, 0.f, 0.f);
            if (row0 + r < NNODE)
                v = *(const float4*)(x + (size_t)(row0 + r) * FEAT + k0 + c);
            xs[r][c]   = v.x; xs[r][c+1] = v.y;
            xs[r][c+2] = v.z; xs[r][c+3] = v.w;
        }
        {
            int r = tid >> 4;
            int c = (tid & 15) * 8;
            size_t off = (size_t)(k0 + r) * FEAT + c;
            *(float4*)&wsl[r][c]     = *(const float4*)(Wl + off);
            *(float4*)&wsl[r][c + 4] = *(const float4*)(Wl + off + 4);
            *(float4*)&wsr[r][c]     = *(const float4*)(Wr + off);
            *(float4*)&wsr[r][c + 4] = *(const float4*)(Wr + off + 4);
        }
        __syncthreads();

        #pragma unroll
        for (int kk = 0; kk < 16; kk++) {
            float a[4], bl[8], br[8];
            #pragma unroll
            for (int i = 0; i < 4; i++) a[i] = xs[ty * 4 + i][kk];
            #pragma unroll
            for (int j = 0; j < 8; j++) { bl[j] = wsl[kk][tx * 8 + j];
                                          br[j] = wsr[kk][tx * 8 + j]; }
            #pragma unroll
            for (int i = 0; i < 4; i++)
                #pragma unroll
                for (int j = 0; j < 8; j++) {
                    accl[i][j] += a[i] * bl[j];
                    accr[i][j] += a[i] * br[j];
                }
        }
        __syncthreads();
    }

    #pragma unroll
    for (int i = 0; i < 4; i++) {
        int r = row0 + ty * 4 + i;
        if (r < NNODE) {
            size_t off = (size_t)r * FEAT + tx * 8;
            *(float4*)(g_xl + off)     = make_float4(accl[i][0], accl[i][1], accl[i][2], accl[i][3]);
            *(float4*)(g_xl + off + 4) = make_float4(accl[i][4], accl[i][5], accl[i][6], accl[i][7]);
            *(float4*)(g_xr + off)     = make_float4(accr[i][0], accr[i][1], accr[i][2], accr[i][3]);
            *(float4*)(g_xr + off + 4) = make_float4(accr[i][4], accr[i][5], accr[i][6], accr[i][7]);
        }
    }
}

// ---------------------------------------------------------------
// K2: one warp per edge.  logits -> exp -> store; atomicAdd to den.
// Max-subtraction elided: exp(l)/sum exp(l) == softmax exactly
// (logits O(6) here; no fp32 overflow risk).
// ---------------------------------------------------------------
__global__ void k_edge_logits(const float* __restrict__ att) {
    int w    = (blockIdx.x * blockDim.x + threadIdx.x) >> 5;
    int lane = threadIdx.x & 31;
    if (w >= ETOT) return;

    int s = 0, d = 0;
    if (lane == 0) {
        if (w < NEDGE) { s = g_ei32[w]; d = g_ei32[NEDGE + w]; }
        else           { s = d = w - NEDGE; }
    }
    s = __shfl_sync(0xffffffffu, s, 0);
    d = __shfl_sync(0xffffffffu, d, 0);

    float4 a = ((const float4*)g_xl)[(size_t)s * 32 + lane];
    float4 b = ((const float4*)g_xr)[(size_t)d * 32 + lane];
    float4 v;
    v.x = a.x + b.x; v.y = a.y + b.y; v.z = a.z + b.z; v.w = a.w + b.w;
    v.x = v.x > 0.f ? v.x : NEG_SLOPE * v.x;
    v.y = v.y > 0.f ? v.y : NEG_SLOPE * v.y;
    v.z = v.z > 0.f ? v.z : NEG_SLOPE * v.z;
    v.w = v.w > 0.f ? v.w : NEG_SLOPE * v.w;

    float4 at = __ldg((const float4*)att + lane);
    float p = v.x * at.x + v.y * at.y + v.z * at.z + v.w * at.w;

    p += __shfl_down_sync(0xffffffffu, p, 4, 8);
    p += __shfl_down_sync(0xffffffffu, p, 2, 8);
    p += __shfl_down_sync(0xffffffffu, p, 1, 8);

    if ((lane & 7) == 0) {
        int h = lane >> 3;
        float ex = __expf(p);
        g_ex[(size_t)w * HH + h] = ex;
        atomicAdd(&g_den[(size_t)d * HH + h], ex);
    }
}

// ---------------------------------------------------------------
// K3: one warp per edge.  alpha = ex/den; write alpha output
// (alpha_out == nullptr -> discard to g_alpha_sink); scatter
// alpha * xl[src] with red.add.v4.f32 (4x fewer L2 RMW ops).
// ---------------------------------------------------------------
__global__ void k_edge_scatter(float* __restrict__ out_acc,
                               float* __restrict__ alpha_out) {
    int w    = (blockIdx.x * blockDim.x + threadIdx.x) >> 5;
    int lane = threadIdx.x & 31;
    if (w >= ETOT) return;

    int s = 0, d = 0;
    if (lane == 0) {
        if (w < NEDGE) { s = g_ei32[w]; d = g_ei32[NEDGE + w]; }
        else           { s = d = w - NEDGE; }
    }
    s = __shfl_sync(0xffffffffu, s, 0);
    d = __shfl_sync(0xffffffffu, d, 0);

    int h = lane >> 3;
    float ex  = g_ex[(size_t)w * HH + h];
    float den = g_den[(size_t)d * HH + h];
    float alpha = ex / den;

    if ((lane & 7) == 0) {
        float* ap = alpha_out ? alpha_out : g_alpha_sink;
        ap[(size_t)w * HH + h] = alpha;
    }

    float4 a = ((const float4*)g_xl)[(size_t)s * 32 + lane];
    float* p = out_acc + (size_t)d * FEAT + lane * 4;
    asm volatile("red.global.add.v4.f32 [%0], {%1,%2,%3,%4};"
                 :: "l"(p), "f"(a.x * alpha), "f"(a.y * alpha),
                    "f"(a.z * alpha), "f"(a.w * alpha)
                 : "memory");
}

// ---------------------------------------------------------------
// K4: out = relu(acc + bias), float4-vectorized
// ---------------------------------------------------------------
__global__ void k_final(float4* __restrict__ out, const float4* __restrict__ bias) {
    int i = blockIdx.x * blockDim.x + threadIdx.x;
    if (i < NNODE * (FEAT / 4)) {
        float4 v = out[i];
        float4 b = __ldg(bias + (i & (FEAT / 4 - 1)));
        v.x = v.x + b.x; v.y = v.y + b.y; v.z = v.z + b.z; v.w = v.w + b.w;
        v.x = v.x > 0.f ? v.x : 0.f;
        v.y = v.y > 0.f ? v.y : 0.f;
        v.z = v.z > 0.f ? v.z : 0.f;
        v.w = v.w > 0.f ? v.w : 0.f;
        out[i] = v;
    }
}

// ---------------------------------------------------------------
extern "C" void kernel_launch(void* const* d_in, const int* in_sizes, int n_in,
                              void* d_out, int out_size) {
    const float* x    = (const float*)d_in[0];
    const void*  ei   = d_in[1];                    // int32 or int64, detected on device
    const float* Wl   = (const float*)d_in[2];
    const float* Wr   = (const float*)d_in[3];
    const float* att  = (const float*)d_in[4];
    const float* bias = (const float*)d_in[5];

    float* out = (float*)d_out;                     // [N, 128]
    float* alpha_out = (out_size >= NNODE * FEAT + ETOT * HH)
                     ? out + (size_t)NNODE * FEAT   // [ETOT, 4]
                     : nullptr;

    k_detect<<<1, 32>>>(ei);
    k_convert<<<(2 * NEDGE + 255) / 256, 256>>>(ei);

    k_zero<<<(NNODE * FEAT + 255) / 256, 256>>>(out);

    k_gemm<<<(NNODE + 63) / 64, 256>>>(x, Wl, Wr);

    int edge_blocks = (ETOT * 32 + 255) / 256;      // 1 warp per edge
    k_edge_logits<<<edge_blocks, 256>>>(att);
    k_edge_scatter<<<edge_blocks, 256>>>(out, alpha_out);

    k_final<<<(NNODE * FEAT / 4 + 255) / 256, 256>>>((float4*)out, (const float4*)bias);
}